// round 3
// baseline (speedup 1.0000x reference)
#include <cuda_runtime.h>
#include <math.h>

#define NB 32
#define NT 512
#define NE 300
#define NH 512
#define NG 2048   // 4*NH

#define NCTA_B 128
#define THR_B  256

#define HS_STRIDE 36          // floats per h row (32 used)
#define US_STRIDE 18          // u64 per U row (16 used)
#define RED_ROW   520         // floats per kt row (512 used)

typedef unsigned long long u64;

// ---------------------------------------------------------------------------
// f32x2 helpers (Blackwell packed fp32 — 2x FFMA throughput, full precision)
// ---------------------------------------------------------------------------
__device__ __forceinline__ u64 pack2(float lo, float hi) {
    u64 r; asm("mov.b64 %0, {%1,%2};" : "=l"(r) : "f"(lo), "f"(hi)); return r;
}
__device__ __forceinline__ void fma2(u64& d, u64 a, u64 b) {
    asm("fma.rn.f32x2 %0, %1, %2, %0;" : "+l"(d) : "l"(a), "l"(b));
}
__device__ __forceinline__ float2 unpack2(u64 v) {
    float2 f; asm("mov.b64 {%0,%1}, %2;" : "=f"(f.x), "=f"(f.y) : "l"(v)); return f;
}

__device__ __forceinline__ float fast_sig(float x) {
    float e = __expf(-x);
    return __fdividef(1.f, 1.f + e);
}
__device__ __forceinline__ float fast_tanh(float x) {
    float e = __expf(2.f * x);              // inf-safe: ->1 / ->-1 at extremes
    return 1.f - 2.f * __fdividef(1.f, e + 1.f);
}

// Scratch (device globals: allocation-free rule)
// xz layout: [t][j][b][gate]  (gate fastest -> one float4 per (t,j,b))
__device__ float g_xz[(size_t)NT * NH * NB * 4];
__device__ float g_h[2][NH * NB];              // ping-pong h, [k][b]
__device__ unsigned int g_bar;

// ---------------------------------------------------------------------------
// Kernel A: z[t][n][b] = sum_k emb[tok(b,t)][k] * W[k][n] + bias[n]
// Tiles 64(M)x64(N), BK=25. Also zeroes g_h / g_bar (replaces init kernel).
// ---------------------------------------------------------------------------
__global__ __launch_bounds__(256) void xz_kernel(
    const int* __restrict__ tokens, const float* __restrict__ emb,
    const float* __restrict__ W, const float* __restrict__ bias)
{
    __shared__ float As[25 * 68];        // [kk][m], stride 68
    __shared__ u64   Bs2[25 * 68];       // [kk][n] duplicated pairs, stride 68
    __shared__ int   toks[64];

    int tid = threadIdx.x;
    int m0 = blockIdx.y * 64;
    int n0 = blockIdx.x * 64;

    // init duty: zero h ping-pong + barrier counter (32 blocks x 256 thr x 16B)
    if (blockIdx.x == 0 && blockIdx.y < 32) {
        int i = blockIdx.y * 256 + tid;            // 0..8191
        ((float4*)g_h)[i] = make_float4(0.f, 0.f, 0.f, 0.f);
        if (i == 0) g_bar = 0u;
    }

    if (tid < 64) {
        int m = m0 + tid;                               // m = t*32 + b
        toks[tid] = tokens[(m & 31) * NT + (m >> 5)];   // tokens[b][t]
    }
    __syncthreads();

    int tm = tid & 15, tn = tid >> 4;
    u64 acc2[2][4];
    #pragma unroll
    for (int p = 0; p < 2; ++p)
        #pragma unroll
        for (int j = 0; j < 4; ++j) acc2[p][j] = 0ull;

    for (int k0 = 0; k0 < NE; k0 += 25) {
        for (int idx = tid; idx < 64 * 25; idx += 256) {
            int m = idx / 25, kk = idx - m * 25;
            As[kk * 68 + m] = emb[(size_t)toks[m] * NE + k0 + kk];
        }
        for (int idx = tid; idx < 25 * 64; idx += 256) {
            int kk = idx >> 6, n = idx & 63;
            float w = W[(size_t)(k0 + kk) * NG + n0 + n];
            Bs2[kk * 68 + n] = pack2(w, w);
        }
        __syncthreads();

        #pragma unroll
        for (int kk = 0; kk < 25; ++kk) {
            float4 av = *(const float4*)&As[kk * 68 + tm * 4];
            ulonglong2 b01 = *(const ulonglong2*)&Bs2[kk * 68 + tn * 4];
            ulonglong2 b23 = *(const ulonglong2*)&Bs2[kk * 68 + tn * 4 + 2];
            u64 ap[2] = { pack2(av.x, av.y), pack2(av.z, av.w) };
            u64 bd[4] = { b01.x, b01.y, b23.x, b23.y };
            #pragma unroll
            for (int p = 0; p < 2; ++p)
                #pragma unroll
                for (int j = 0; j < 4; ++j)
                    fma2(acc2[p][j], ap[p], bd[j]);
        }
        __syncthreads();
    }

    #pragma unroll
    for (int j = 0; j < 4; ++j) {
        int n = n0 + tn * 4 + j;
        int gate = n >> 9, col = n & 511;
        float bb = bias[n];
        #pragma unroll
        for (int p = 0; p < 2; ++p) {
            float2 v = unpack2(acc2[p][j]);
            int mi0 = m0 + tm * 4 + p * 2;
            int t0 = mi0 >> 5, b0 = mi0 & 31;
            int t1 = (mi0 + 1) >> 5, b1 = (mi0 + 1) & 31;
            // xz[t][col][b][gate]
            __stcs(&g_xz[(((size_t)t0 * NH + col) * NB + b0) * 4 + gate], v.x + bb);
            __stcs(&g_xz[(((size_t)t1 * NH + col) * NB + b1) * 4 + gate], v.y + bb);
        }
    }
}

// ---------------------------------------------------------------------------
// Kernel B: persistent LSTM. 128 CTAs x 256 thr; CTA owns 4 h-cols across 4
// gates (16 U cols, duplicated f32x2 pairs in smem). Thread tile 4b x 8c,
// K-split 16 + smem reduce. Broadcast-friendly LDS pattern.
// ---------------------------------------------------------------------------
__global__ __launch_bounds__(THR_B) void lstm_kernel(
    const float* __restrict__ U, float* __restrict__ out)
{
    extern __shared__ float sm[];
    u64*   us2 = (u64*)sm;                      // [512][US_STRIDE] u64
    float* hs  = (float*)(us2 + NH * US_STRIDE);// [512][HS_STRIDE]
    float* red = hs + NH * HS_STRIDE;           // [16][RED_ROW]
    float* zs  = red + 16 * RED_ROW;            // [512]
    float* cs  = zs + 512;                      // [128]

    int tid = threadIdx.x;
    int cta = blockIdx.x;
    int j0 = cta * 4;

    // Load U slice as duplicated pairs: col c = gate*4+jj -> U[k][gate*512+j0+jj]
    for (int idx = tid; idx < NH * 16; idx += THR_B) {
        int k = idx >> 4, c = idx & 15;
        int col = (c >> 2) * NH + j0 + (c & 3);
        float u = U[(size_t)k * NG + col];
        us2[k * US_STRIDE + c] = pack2(u, u);
    }
    if (tid < 128) cs[tid] = 0.f;
    __syncthreads();

    // thread tile: 4 batches x 8 cols, 16-way K split
    int kt = tid >> 4, ot = tid & 15;
    int b0 = (ot & 7) * 4;                      // 8 b-tiles of 4
    int c0 = (ot >> 3) * 8;                     // 2 c-tiles of 8
    int kbase = kt * 32;
    int jj = tid >> 5, bb = tid & 31;           // gates mapping (tid<128)

    for (int t = 0; t < NT; ++t) {
        int parity = t & 1;

        // Prefetch xz (one coalesced float4 per (j,b) thread)
        float4 xv = make_float4(0.f, 0.f, 0.f, 0.f);
        if (tid < 128)
            xv = __ldcs((const float4*)&g_xz[(((size_t)t * NH + j0 + jj) * NB + bb) * 4]);

        // Copy h from global (L2-coherent) into smem, vectorized
        const float4* gh4 = (const float4*)g_h[parity];
        for (int i4 = tid; i4 < (NH * NB) / 4; i4 += THR_B) {
            float4 v = __ldcg(gh4 + i4);
            int base = i4 * 4;
            int k = base >> 5, b = base & 31;
            *(float4*)(hs + k * HS_STRIDE + b) = v;
        }
        __syncthreads();

        // Partial GEMM over K slice of 32: per k, 1 h-LDS.128 + 4 U-LDS.128
        // for 16 FFMA2 (64 MACs)
        u64 acc2[2][8];
        #pragma unroll
        for (int i = 0; i < 2; ++i)
            #pragma unroll
            for (int j = 0; j < 8; ++j) acc2[i][j] = 0ull;

        #pragma unroll 4
        for (int k = 0; k < 32; ++k) {
            int kk = kbase + k;
            float4 hv = *(const float4*)(hs + kk * HS_STRIDE + b0);
            const u64* urow = us2 + kk * US_STRIDE + c0;
            ulonglong2 ua = *(const ulonglong2*)urow;
            ulonglong2 ub = *(const ulonglong2*)(urow + 2);
            ulonglong2 uc = *(const ulonglong2*)(urow + 4);
            ulonglong2 ud = *(const ulonglong2*)(urow + 6);
            u64 hp[2] = { pack2(hv.x, hv.y), pack2(hv.z, hv.w) };
            u64 up[8] = { ua.x, ua.y, ub.x, ub.y, uc.x, uc.y, ud.x, ud.y };
            #pragma unroll
            for (int i = 0; i < 2; ++i)
                #pragma unroll
                for (int j = 0; j < 8; ++j)
                    fma2(acc2[i][j], hp[i], up[j]);
        }

        // K-split partials: red[kt][c*32 + b], vectorized 4-batch stores
        #pragma unroll
        for (int j = 0; j < 8; ++j) {
            float2 v0 = unpack2(acc2[0][j]);
            float2 v1 = unpack2(acc2[1][j]);
            *(float4*)(red + kt * RED_ROW + (c0 + j) * 32 + b0) =
                make_float4(v0.x, v0.y, v1.x, v1.y);
        }
        __syncthreads();

        #pragma unroll
        for (int r = 0; r < 2; ++r) {
            int o = tid * 2 + r;
            float s = 0.f;
            #pragma unroll
            for (int q = 0; q < 16; ++q) s += red[q * RED_ROW + o];
            zs[o] = s;
        }
        __syncthreads();

        // Gates + state update (thread = (jj, bb), 128 threads)
        if (tid < 128) {
            float zi = zs[(0 * 4 + jj) * 32 + bb] + xv.x;
            float zf = zs[(1 * 4 + jj) * 32 + bb] + xv.y;
            float zg = zs[(2 * 4 + jj) * 32 + bb] + xv.z;
            float zo = zs[(3 * 4 + jj) * 32 + bb] + xv.w;

            float ig = fast_sig(zi);
            float fg = fast_sig(zf);
            float gg = fast_tanh(zg);
            float og = fast_sig(zo);

            float cn = fg * cs[tid] + ig * gg;
            cs[tid] = cn;
            float hn = og * fast_tanh(cn);

            if (t == NT - 1) {
                out[bb * NH + (j0 + jj)] = hn;             // hidden [B,H]
                out[NB * NH + bb * NH + (j0 + jj)] = cn;   // cell   [B,H]
            } else {
                g_h[parity ^ 1][(j0 + jj) * NB + bb] = hn;
            }
        }

        // Grid-wide barrier
        if (t < NT - 1) {
            __threadfence();
            __syncthreads();
            if (tid == 0) {
                atomicAdd(&g_bar, 1u);
                unsigned target = (unsigned)NCTA_B * (unsigned)(t + 1);
                while (*((volatile unsigned int*)&g_bar) < target) { }
            }
            __syncthreads();
        }
    }
}

// ---------------------------------------------------------------------------
extern "C" void kernel_launch(void* const* d_in, const int* in_sizes, int n_in,
                              void* d_out, int out_size) {
    const int*   tokens = (const int*)d_in[0];
    const float* emb    = (const float*)d_in[1];
    const float* W      = (const float*)d_in[2];
    const float* U      = (const float*)d_in[3];
    const float* bias   = (const float*)d_in[4];
    float* out = (float*)d_out;

    dim3 ga(NG / 64, (NB * NT) / 64);   // (32, 256)
    xz_kernel<<<ga, 256>>>(tokens, emb, W, bias);

    int smem = (int)(NH * US_STRIDE * sizeof(u64) +
                     (NH * HS_STRIDE + 16 * RED_ROW + 512 + 128) * sizeof(float));
    cudaFuncSetAttribute(lstm_kernel, cudaFuncAttributeMaxDynamicSharedMemorySize, smem);
    lstm_kernel<<<NCTA_B, THR_B, smem>>>(U, out);
}

// round 4
// speedup vs baseline: 1.0265x; 1.0265x over previous
#include <cuda_runtime.h>
#include <math.h>

#define NB 32
#define NT 512
#define NE 300
#define NH 512
#define NG 2048   // 4*NH

#define NCTA_B 128
#define THR_B  256

#define HS_STRIDE 36          // floats per h row (32 used)
#define US_STRIDE 18          // u64 per U row (16 used)
#define RED_ROW   520         // floats per kt row (512 used)

typedef unsigned long long u64;

// ---------------------------------------------------------------------------
// f32x2 helpers (Blackwell packed fp32 — 2x FFMA throughput, full precision)
// ---------------------------------------------------------------------------
__device__ __forceinline__ u64 pack2(float lo, float hi) {
    u64 r; asm("mov.b64 %0, {%1,%2};" : "=l"(r) : "f"(lo), "f"(hi)); return r;
}
__device__ __forceinline__ void fma2(u64& d, u64 a, u64 b) {
    asm("fma.rn.f32x2 %0, %1, %2, %0;" : "+l"(d) : "l"(a), "l"(b));
}
__device__ __forceinline__ float2 unpack2(u64 v) {
    float2 f; asm("mov.b64 {%0,%1}, %2;" : "=f"(f.x), "=f"(f.y) : "l"(v)); return f;
}

__device__ __forceinline__ float fast_sig(float x) {
    float e = __expf(-x);
    return __fdividef(1.f, 1.f + e);
}
__device__ __forceinline__ float fast_tanh(float x) {
    float e = __expf(2.f * x);              // inf-safe: ->1 / ->-1 at extremes
    return 1.f - 2.f * __fdividef(1.f, e + 1.f);
}

// Release-increment / acquire-poll (grid.sync pattern, no gpu membar / IVALL)
__device__ __forceinline__ void bar_release_add(unsigned int* p) {
    asm volatile("red.release.gpu.global.add.u32 [%0], %1;"
                 :: "l"(p), "r"(1u) : "memory");
}
__device__ __forceinline__ unsigned int bar_acquire_ld(unsigned int* p) {
    unsigned int v;
    asm volatile("ld.acquire.gpu.global.u32 %0, [%1];"
                 : "=r"(v) : "l"(p) : "memory");
    return v;
}

// Scratch (device globals: allocation-free rule)
// xz layout: [t][j][b][gate]  (gate fastest -> one float4 per (t,j,b))
__device__ float g_xz[(size_t)NT * NH * NB * 4];
__device__ float g_h[2][NH * NB];              // ping-pong h, [k][b]
__device__ unsigned int g_bar;

// ---------------------------------------------------------------------------
// Kernel A: z[t][n][b] = sum_k emb[tok(b,t)][k] * W[k][n] + bias[n]
// Tiles 64(M)x64(N), BK=25. Also zeroes g_h / g_bar (replaces init kernel).
// ---------------------------------------------------------------------------
__global__ __launch_bounds__(256) void xz_kernel(
    const int* __restrict__ tokens, const float* __restrict__ emb,
    const float* __restrict__ W, const float* __restrict__ bias)
{
    __shared__ float As[25 * 68];        // [kk][m], stride 68
    __shared__ u64   Bs2[25 * 68];       // [kk][n] duplicated pairs, stride 68
    __shared__ int   toks[64];

    int tid = threadIdx.x;
    int m0 = blockIdx.y * 64;
    int n0 = blockIdx.x * 64;

    // init duty: zero h ping-pong + barrier counter
    if (blockIdx.x == 0 && blockIdx.y < 32) {
        int i = blockIdx.y * 256 + tid;            // 0..8191
        ((float4*)g_h)[i] = make_float4(0.f, 0.f, 0.f, 0.f);
        if (i == 0) g_bar = 0u;
    }

    if (tid < 64) {
        int m = m0 + tid;                               // m = t*32 + b
        toks[tid] = tokens[(m & 31) * NT + (m >> 5)];   // tokens[b][t]
    }
    __syncthreads();

    int tm = tid & 15, tn = tid >> 4;
    u64 acc2[2][4];
    #pragma unroll
    for (int p = 0; p < 2; ++p)
        #pragma unroll
        for (int j = 0; j < 4; ++j) acc2[p][j] = 0ull;

    for (int k0 = 0; k0 < NE; k0 += 25) {
        for (int idx = tid; idx < 64 * 25; idx += 256) {
            int m = idx / 25, kk = idx - m * 25;
            As[kk * 68 + m] = emb[(size_t)toks[m] * NE + k0 + kk];
        }
        for (int idx = tid; idx < 25 * 64; idx += 256) {
            int kk = idx >> 6, n = idx & 63;
            float w = W[(size_t)(k0 + kk) * NG + n0 + n];
            Bs2[kk * 68 + n] = pack2(w, w);
        }
        __syncthreads();

        #pragma unroll
        for (int kk = 0; kk < 25; ++kk) {
            float4 av = *(const float4*)&As[kk * 68 + tm * 4];
            ulonglong2 b01 = *(const ulonglong2*)&Bs2[kk * 68 + tn * 4];
            ulonglong2 b23 = *(const ulonglong2*)&Bs2[kk * 68 + tn * 4 + 2];
            u64 ap[2] = { pack2(av.x, av.y), pack2(av.z, av.w) };
            u64 bd[4] = { b01.x, b01.y, b23.x, b23.y };
            #pragma unroll
            for (int p = 0; p < 2; ++p)
                #pragma unroll
                for (int j = 0; j < 4; ++j)
                    fma2(acc2[p][j], ap[p], bd[j]);
        }
        __syncthreads();
    }

    #pragma unroll
    for (int j = 0; j < 4; ++j) {
        int n = n0 + tn * 4 + j;
        int gate = n >> 9, col = n & 511;
        float bb = bias[n];
        #pragma unroll
        for (int p = 0; p < 2; ++p) {
            float2 v = unpack2(acc2[p][j]);
            int mi0 = m0 + tm * 4 + p * 2;
            int t0 = mi0 >> 5, b0 = mi0 & 31;
            int t1 = (mi0 + 1) >> 5, b1 = (mi0 + 1) & 31;
            __stcs(&g_xz[(((size_t)t0 * NH + col) * NB + b0) * 4 + gate], v.x + bb);
            __stcs(&g_xz[(((size_t)t1 * NH + col) * NB + b1) * 4 + gate], v.y + bb);
        }
    }
}

// ---------------------------------------------------------------------------
// Kernel B: persistent LSTM. 128 CTAs x 256 thr; CTA owns 4 h-cols across 4
// gates. Interleaved 16-way K-split (k = kt + 16*i) so the h broadcast is
// chunk-pipelined under the GEMM. Release/acquire grid barrier (no membar).
// ---------------------------------------------------------------------------
__global__ __launch_bounds__(THR_B) void lstm_kernel(
    const float* __restrict__ U, float* __restrict__ out)
{
    extern __shared__ float sm[];
    u64*   us2 = (u64*)sm;                      // [512][US_STRIDE] u64
    float* hs  = (float*)(us2 + NH * US_STRIDE);// [512][HS_STRIDE]
    float* red = hs + NH * HS_STRIDE;           // [16][RED_ROW]
    float* zs  = red + 16 * RED_ROW;            // [512]
    float* cs  = zs + 512;                      // [128]

    int tid = threadIdx.x;
    int cta = blockIdx.x;
    int j0 = cta * 4;

    // Load U slice as duplicated pairs: col c = gate*4+jj -> U[k][gate*512+j0+jj]
    for (int idx = tid; idx < NH * 16; idx += THR_B) {
        int k = idx >> 4, c = idx & 15;
        int col = (c >> 2) * NH + j0 + (c & 3);
        float u = U[(size_t)k * NG + col];
        us2[k * US_STRIDE + c] = pack2(u, u);
    }
    if (tid < 128) cs[tid] = 0.f;
    __syncthreads();

    // thread tile: 4 batches x 8 cols; interleaved K split (stride 16)
    int kt = tid >> 4, ot = tid & 15;
    int b0 = (ot & 7) * 4;                      // 8 b-tiles of 4
    int c0 = (ot >> 3) * 8;                     // 2 c-tiles of 8
    int jj = tid >> 5, bb = tid & 31;           // gates mapping (tid<128)

    for (int t = 0; t < NT; ++t) {
        int parity = t & 1;

        // Prefetch xz (one coalesced float4 per (j,b) thread)
        float4 xv = make_float4(0.f, 0.f, 0.f, 0.f);
        if (tid < 128)
            xv = __ldcs((const float4*)&g_xz[(((size_t)t * NH + j0 + jj) * NB + bb) * 4]);

        const float4* gh4 = (const float4*)g_h[parity];

        // ---- chunk 0 copy (rows 0..127) ----
        #pragma unroll
        for (int r = 0; r < 4; ++r) {
            int f = r * 256 + tid;              // float4 index in chunk
            float4 v = __ldcg(gh4 + f);
            int base = f * 4;
            *(float4*)(hs + (base >> 5) * HS_STRIDE + (base & 31)) = v;
        }
        __syncthreads();

        u64 acc2[2][8];
        #pragma unroll
        for (int i = 0; i < 2; ++i)
            #pragma unroll
            for (int j = 0; j < 8; ++j) acc2[i][j] = 0ull;

        // ---- pipelined chunks: prefetch next, GEMM current ----
        #pragma unroll
        for (int c = 0; c < 4; ++c) {
            float4 pre[4];
            if (c < 3) {
                #pragma unroll
                for (int r = 0; r < 4; ++r)
                    pre[r] = __ldcg(gh4 + (c + 1) * 1024 + r * 256 + tid);
            }

            // GEMM over this chunk: k = kt + 16*(8c + i)
            #pragma unroll
            for (int i = 0; i < 8; ++i) {
                int kk = 128 * c + 16 * i + kt;
                float4 hv = *(const float4*)(hs + kk * HS_STRIDE + b0);
                const u64* urow = us2 + kk * US_STRIDE + c0;
                ulonglong2 ua = *(const ulonglong2*)urow;
                ulonglong2 ub = *(const ulonglong2*)(urow + 2);
                ulonglong2 uc = *(const ulonglong2*)(urow + 4);
                ulonglong2 ud = *(const ulonglong2*)(urow + 6);
                u64 hp[2] = { pack2(hv.x, hv.y), pack2(hv.z, hv.w) };
                u64 up[8] = { ua.x, ua.y, ub.x, ub.y, uc.x, uc.y, ud.x, ud.y };
                #pragma unroll
                for (int p = 0; p < 2; ++p)
                    #pragma unroll
                    for (int j = 0; j < 8; ++j)
                        fma2(acc2[p][j], hp[p], up[j]);
            }

            if (c < 3) {
                #pragma unroll
                for (int r = 0; r < 4; ++r) {
                    int f = (c + 1) * 1024 + r * 256 + tid;
                    int base = f * 4;
                    *(float4*)(hs + (base >> 5) * HS_STRIDE + (base & 31)) = pre[r];
                }
                __syncthreads();
            }
        }

        // K-split partials: red[kt][c*32 + b], vectorized 4-batch stores
        #pragma unroll
        for (int j = 0; j < 8; ++j) {
            float2 v0 = unpack2(acc2[0][j]);
            float2 v1 = unpack2(acc2[1][j]);
            *(float4*)(red + kt * RED_ROW + (c0 + j) * 32 + b0) =
                make_float4(v0.x, v0.y, v1.x, v1.y);
        }
        __syncthreads();

        #pragma unroll
        for (int r = 0; r < 2; ++r) {
            int o = tid * 2 + r;
            float s = 0.f;
            #pragma unroll
            for (int q = 0; q < 16; ++q) s += red[q * RED_ROW + o];
            zs[o] = s;
        }
        __syncthreads();

        // Gates + state update (thread = (jj, bb), 128 threads)
        if (tid < 128) {
            float zi = zs[(0 * 4 + jj) * 32 + bb] + xv.x;
            float zf = zs[(1 * 4 + jj) * 32 + bb] + xv.y;
            float zg = zs[(2 * 4 + jj) * 32 + bb] + xv.z;
            float zo = zs[(3 * 4 + jj) * 32 + bb] + xv.w;

            float ig = fast_sig(zi);
            float fg = fast_sig(zf);
            float gg = fast_tanh(zg);
            float og = fast_sig(zo);

            float cn = fg * cs[tid] + ig * gg;
            cs[tid] = cn;
            float hn = og * fast_tanh(cn);

            if (t == NT - 1) {
                out[bb * NH + (j0 + jj)] = hn;             // hidden [B,H]
                out[NB * NH + bb * NH + (j0 + jj)] = cn;   // cell   [B,H]
            } else {
                __stcg(&g_h[parity ^ 1][(j0 + jj) * NB + bb], hn);
            }
        }

        // Grid-wide barrier: release-increment, acquire-poll
        if (t < NT - 1) {
            __syncthreads();
            if (tid == 0) {
                bar_release_add(&g_bar);
                unsigned target = (unsigned)NCTA_B * (unsigned)(t + 1);
                while (bar_acquire_ld(&g_bar) < target) { }
            }
            __syncthreads();
        }
    }
}

// ---------------------------------------------------------------------------
extern "C" void kernel_launch(void* const* d_in, const int* in_sizes, int n_in,
                              void* d_out, int out_size) {
    const int*   tokens = (const int*)d_in[0];
    const float* emb    = (const float*)d_in[1];
    const float* W      = (const float*)d_in[2];
    const float* U      = (const float*)d_in[3];
    const float* bias   = (const float*)d_in[4];
    float* out = (float*)d_out;

    dim3 ga(NG / 64, (NB * NT) / 64);   // (32, 256)
    xz_kernel<<<ga, 256>>>(tokens, emb, W, bias);

    int smem = (int)(NH * US_STRIDE * sizeof(u64) +
                     (NH * HS_STRIDE + 16 * RED_ROW + 512 + 128) * sizeof(float));
    cudaFuncSetAttribute(lstm_kernel, cudaFuncAttributeMaxDynamicSharedMemorySize, smem);
    lstm_kernel<<<NCTA_B, THR_B, smem>>>(U, out);
}

// round 5
// speedup vs baseline: 1.1081x; 1.0795x over previous
#include <cuda_runtime.h>
#include <math.h>

#define NB 32
#define NT 512
#define NE 300
#define NH 512
#define NG 2048   // 4*NH

#define NCTA_B 128
#define THR_B  512

#define HS_STRIDE 36          // floats per h row (32 used)
#define US_STRIDE 18          // u64 per U row (16 used)
#define RED_ROW   520         // floats per kt row (512 used)

typedef unsigned long long u64;

// ---------------------------------------------------------------------------
// f32x2 helpers (Blackwell packed fp32 — 2x FFMA throughput, full precision)
// ---------------------------------------------------------------------------
__device__ __forceinline__ u64 pack2(float lo, float hi) {
    u64 r; asm("mov.b64 %0, {%1,%2};" : "=l"(r) : "f"(lo), "f"(hi)); return r;
}
__device__ __forceinline__ void fma2(u64& d, u64 a, u64 b) {
    asm("fma.rn.f32x2 %0, %1, %2, %0;" : "+l"(d) : "l"(a), "l"(b));
}
__device__ __forceinline__ float2 unpack2(u64 v) {
    float2 f; asm("mov.b64 {%0,%1}, %2;" : "=f"(f.x), "=f"(f.y) : "l"(v)); return f;
}

__device__ __forceinline__ float fast_sig(float x) {
    float e = __expf(-x);
    return __fdividef(1.f, 1.f + e);
}
__device__ __forceinline__ float fast_tanh(float x) {
    float e = __expf(2.f * x);              // inf-safe: ->1 / ->-1 at extremes
    return 1.f - 2.f * __fdividef(1.f, e + 1.f);
}

// Release-increment / acquire-poll (grid.sync pattern, no gpu membar / IVALL)
__device__ __forceinline__ void bar_release_add(unsigned int* p) {
    asm volatile("red.release.gpu.global.add.u32 [%0], %1;"
                 :: "l"(p), "r"(1u) : "memory");
}
__device__ __forceinline__ unsigned int bar_acquire_ld(unsigned int* p) {
    unsigned int v;
    asm volatile("ld.acquire.gpu.global.u32 %0, [%1];"
                 : "=r"(v) : "l"(p) : "memory");
    return v;
}

// Scratch (device globals: allocation-free rule)
// xz layout: [t][j][b][gate]  (gate fastest -> one float4 per (t,j,b))
__device__ float g_xz[(size_t)NT * NH * NB * 4];
__device__ float g_h[2][NH * NB];              // ping-pong h, [k][b]
__device__ unsigned int g_bar;

// ---------------------------------------------------------------------------
// Kernel A: z[t][n][b] = sum_k emb[tok(b,t)][k] * W[k][n] + bias[n]
// Tiles 64(M)x64(N), BK=25. Also zeroes g_h / g_bar.
// ---------------------------------------------------------------------------
__global__ __launch_bounds__(256) void xz_kernel(
    const int* __restrict__ tokens, const float* __restrict__ emb,
    const float* __restrict__ W, const float* __restrict__ bias)
{
    __shared__ float As[25 * 68];
    __shared__ u64   Bs2[25 * 68];
    __shared__ int   toks[64];

    int tid = threadIdx.x;
    int m0 = blockIdx.y * 64;
    int n0 = blockIdx.x * 64;

    if (blockIdx.x == 0 && blockIdx.y < 32) {
        int i = blockIdx.y * 256 + tid;
        ((float4*)g_h)[i] = make_float4(0.f, 0.f, 0.f, 0.f);
        if (i == 0) g_bar = 0u;
    }

    if (tid < 64) {
        int m = m0 + tid;
        toks[tid] = tokens[(m & 31) * NT + (m >> 5)];
    }
    __syncthreads();

    int tm = tid & 15, tn = tid >> 4;
    u64 acc2[2][4];
    #pragma unroll
    for (int p = 0; p < 2; ++p)
        #pragma unroll
        for (int j = 0; j < 4; ++j) acc2[p][j] = 0ull;

    for (int k0 = 0; k0 < NE; k0 += 25) {
        for (int idx = tid; idx < 64 * 25; idx += 256) {
            int m = idx / 25, kk = idx - m * 25;
            As[kk * 68 + m] = emb[(size_t)toks[m] * NE + k0 + kk];
        }
        for (int idx = tid; idx < 25 * 64; idx += 256) {
            int kk = idx >> 6, n = idx & 63;
            float w = W[(size_t)(k0 + kk) * NG + n0 + n];
            Bs2[kk * 68 + n] = pack2(w, w);
        }
        __syncthreads();

        #pragma unroll
        for (int kk = 0; kk < 25; ++kk) {
            float4 av = *(const float4*)&As[kk * 68 + tm * 4];
            ulonglong2 b01 = *(const ulonglong2*)&Bs2[kk * 68 + tn * 4];
            ulonglong2 b23 = *(const ulonglong2*)&Bs2[kk * 68 + tn * 4 + 2];
            u64 ap[2] = { pack2(av.x, av.y), pack2(av.z, av.w) };
            u64 bd[4] = { b01.x, b01.y, b23.x, b23.y };
            #pragma unroll
            for (int p = 0; p < 2; ++p)
                #pragma unroll
                for (int j = 0; j < 4; ++j)
                    fma2(acc2[p][j], ap[p], bd[j]);
        }
        __syncthreads();
    }

    #pragma unroll
    for (int j = 0; j < 4; ++j) {
        int n = n0 + tn * 4 + j;
        int gate = n >> 9, col = n & 511;
        float bb = bias[n];
        #pragma unroll
        for (int p = 0; p < 2; ++p) {
            float2 v = unpack2(acc2[p][j]);
            int mi0 = m0 + tm * 4 + p * 2;
            int t0 = mi0 >> 5, b0 = mi0 & 31;
            int t1 = (mi0 + 1) >> 5, b1 = (mi0 + 1) & 31;
            __stcs(&g_xz[(((size_t)t0 * NH + col) * NB + b0) * 4 + gate], v.x + bb);
            __stcs(&g_xz[(((size_t)t1 * NH + col) * NB + b1) * 4 + gate], v.y + bb);
        }
    }
}

// ---------------------------------------------------------------------------
// Kernel B: persistent LSTM. 128 CTAs x 512 thr (16 warps for latency hiding);
// CTA owns 4 h-cols across 4 gates. Warp = one kt slice (interleaved K,
// stride 16). Thread tile 4b x 4c. Chunk-pipelined h broadcast.
// ---------------------------------------------------------------------------
__global__ __launch_bounds__(THR_B) void lstm_kernel(
    const float* __restrict__ U, float* __restrict__ out)
{
    extern __shared__ float sm[];
    u64*   us2 = (u64*)sm;                      // [512][US_STRIDE] u64
    float* hs  = (float*)(us2 + NH * US_STRIDE);// [512][HS_STRIDE]
    float* red = hs + NH * HS_STRIDE;           // [16][RED_ROW]
    float* zs  = red + 16 * RED_ROW;            // [512]
    float* cs  = zs + 512;                      // [128]

    int tid = threadIdx.x;
    int cta = blockIdx.x;
    int j0 = cta * 4;

    // Load U slice as duplicated pairs: col c = gate*4+jj -> U[k][gate*512+j0+jj]
    for (int idx = tid; idx < NH * 16; idx += THR_B) {
        int k = idx >> 4, c = idx & 15;
        int col = (c >> 2) * NH + j0 + (c & 3);
        float u = U[(size_t)k * NG + col];
        us2[k * US_STRIDE + c] = pack2(u, u);
    }
    if (tid < 128) cs[tid] = 0.f;
    __syncthreads();

    // warp = kt (16 K-slices); thread tile 4 batches x 4 cols
    int kt = tid >> 5;                          // warp id
    int ot = tid & 31;
    int b0 = (ot & 7) * 4;                      // 8 b-tiles of 4
    int c0 = (ot >> 3) * 4;                     // 4 c-tiles of 4
    int jj = tid >> 5, bb = tid & 31;           // gates mapping (tid<128): jj = warp 0..3

    for (int t = 0; t < NT; ++t) {
        int parity = t & 1;

        // Prefetch xz (one coalesced float4 per (j,b) thread)
        float4 xv = make_float4(0.f, 0.f, 0.f, 0.f);
        if (tid < 128)
            xv = __ldcs((const float4*)&g_xz[(((size_t)t * NH + j0 + jj) * NB + bb) * 4]);

        const float4* gh4 = (const float4*)g_h[parity];

        // ---- chunk 0 copy (rows 0..127 = 1024 float4, 2 per thread) ----
        #pragma unroll
        for (int r = 0; r < 2; ++r) {
            int f = r * 512 + tid;
            float4 v = __ldcg(gh4 + f);
            int base = f * 4;
            *(float4*)(hs + (base >> 5) * HS_STRIDE + (base & 31)) = v;
        }
        __syncthreads();

        u64 acc2[2][4];
        #pragma unroll
        for (int i = 0; i < 2; ++i)
            #pragma unroll
            for (int j = 0; j < 4; ++j) acc2[i][j] = 0ull;

        // ---- pipelined chunks: prefetch next, GEMM current ----
        // k = kt + 16*(8c + i): each chunk of 128 rows holds 8 iters per warp
        #pragma unroll
        for (int c = 0; c < 4; ++c) {
            float4 pre[2];
            if (c < 3) {
                #pragma unroll
                for (int r = 0; r < 2; ++r)
                    pre[r] = __ldcg(gh4 + (c + 1) * 1024 + r * 512 + tid);
            }

            #pragma unroll
            for (int i = 0; i < 8; ++i) {
                int kk = 128 * c + 16 * i + kt;
                float4 hv = *(const float4*)(hs + kk * HS_STRIDE + b0);
                const u64* urow = us2 + kk * US_STRIDE + c0;
                ulonglong2 ua = *(const ulonglong2*)urow;
                ulonglong2 ub = *(const ulonglong2*)(urow + 2);
                u64 hp[2] = { pack2(hv.x, hv.y), pack2(hv.z, hv.w) };
                u64 up[4] = { ua.x, ua.y, ub.x, ub.y };
                #pragma unroll
                for (int p = 0; p < 2; ++p)
                    #pragma unroll
                    for (int j = 0; j < 4; ++j)
                        fma2(acc2[p][j], hp[p], up[j]);
            }

            if (c < 3) {
                #pragma unroll
                for (int r = 0; r < 2; ++r) {
                    int f = (c + 1) * 1024 + r * 512 + tid;
                    int base = f * 4;
                    *(float4*)(hs + (base >> 5) * HS_STRIDE + (base & 31)) = pre[r];
                }
                __syncthreads();
            }
        }

        // K-split partials: red[kt][c*32 + b]
        #pragma unroll
        for (int j = 0; j < 4; ++j) {
            float2 v0 = unpack2(acc2[0][j]);
            float2 v1 = unpack2(acc2[1][j]);
            *(float4*)(red + kt * RED_ROW + (c0 + j) * 32 + b0) =
                make_float4(v0.x, v0.y, v1.x, v1.y);
        }
        __syncthreads();

        // 512 outputs / 512 threads: 1 each
        {
            int o = tid;
            float s = 0.f;
            #pragma unroll
            for (int q = 0; q < 16; ++q) s += red[q * RED_ROW + o];
            zs[o] = s;
        }
        __syncthreads();

        // Gates + state update (thread = (jj, bb), 128 threads)
        if (tid < 128) {
            float zi = zs[(0 * 4 + jj) * 32 + bb] + xv.x;
            float zf = zs[(1 * 4 + jj) * 32 + bb] + xv.y;
            float zg = zs[(2 * 4 + jj) * 32 + bb] + xv.z;
            float zo = zs[(3 * 4 + jj) * 32 + bb] + xv.w;

            float ig = fast_sig(zi);
            float fg = fast_sig(zf);
            float gg = fast_tanh(zg);
            float og = fast_sig(zo);

            float cn = fg * cs[tid] + ig * gg;
            cs[tid] = cn;
            float hn = og * fast_tanh(cn);

            if (t == NT - 1) {
                out[bb * NH + (j0 + jj)] = hn;             // hidden [B,H]
                out[NB * NH + bb * NH + (j0 + jj)] = cn;   // cell   [B,H]
            } else {
                __stcg(&g_h[parity ^ 1][(j0 + jj) * NB + bb], hn);
            }
        }

        // Grid-wide barrier: release-increment, acquire-poll
        if (t < NT - 1) {
            __syncthreads();
            if (tid == 0) {
                bar_release_add(&g_bar);
                unsigned target = (unsigned)NCTA_B * (unsigned)(t + 1);
                while (bar_acquire_ld(&g_bar) < target) { }
            }
            __syncthreads();
        }
    }
}

// ---------------------------------------------------------------------------
extern "C" void kernel_launch(void* const* d_in, const int* in_sizes, int n_in,
                              void* d_out, int out_size) {
    const int*   tokens = (const int*)d_in[0];
    const float* emb    = (const float*)d_in[1];
    const float* W      = (const float*)d_in[2];
    const float* U      = (const float*)d_in[3];
    const float* bias   = (const float*)d_in[4];
    float* out = (float*)d_out;

    dim3 ga(NG / 64, (NB * NT) / 64);   // (32, 256)
    xz_kernel<<<ga, 256>>>(tokens, emb, W, bias);

    int smem = (int)(NH * US_STRIDE * sizeof(u64) +
                     (NH * HS_STRIDE + 16 * RED_ROW + 512 + 128) * sizeof(float));
    cudaFuncSetAttribute(lstm_kernel, cudaFuncAttributeMaxDynamicSharedMemorySize, smem);
    lstm_kernel<<<NCTA_B, THR_B, smem>>>(U, out);
}